// round 12
// baseline (speedup 1.0000x reference)
#include <cuda_runtime.h>
#include <cstdint>

// Patcher: x (8,3,1024,1024) fp32, patch=24, stride=16, reflect pad m=4.
// out[((b*64+ph)*64+pw)*1728 + (i*24+j)*3 + c] = x[b,c,ry,rx]
//   ry=reflect(ph*16+i-4), rx=reflect(pw*16+j-4); reflect: q<0->-q, q>1023->2046-q.
//
// Direct barrier-free kernel: one thread = one output float4 (x2 grid-stride).
// Stores: consecutive threads -> consecutive float4 -> 4 wavefronts/STG (floor).
// Loads: 4 scalar LDG per f4 from planar input (heavily L2-resident).
// No smem, no barriers; MLP = 8 outstanding loads/thread.

static constexpr unsigned HWu = 1024u * 1024u;
static constexpr long long TOTAL_ELEMS = 56623104LL;
static constexpr unsigned TOTAL_F4 = 14155776u;       // TOTAL_ELEMS / 4
static constexpr unsigned HALF_F4 = TOTAL_F4 / 2u;    // 7,077,888
static constexpr unsigned NBLOCKS = HALF_F4 / 256u;   // 27648 exact

__device__ __forceinline__ int reflect_idx(int q) {
    q = (q < 0) ? -q : q;
    q = (q > 1023) ? (2046 - q) : q;
    return q;
}

__device__ __forceinline__ float4 gather_f4(const float* __restrict__ x,
                                            unsigned idx) {
    // idx -> (b, ph, pw, i, off)
    unsigned patch = idx / 432u;
    unsigned rem   = idx - patch * 432u;
    unsigned i     = rem / 18u;
    unsigned off   = rem - i * 18u;
    unsigned pw  = patch & 63u;
    unsigned phb = patch >> 6;
    unsigned ph  = phb & 63u;
    unsigned b   = phb >> 6;

    int y = reflect_idx((int)(ph << 4) + (int)i - 4);

    unsigned e0 = off << 2;        // element index within row = j*3 + c
    unsigned j  = e0 / 3u;
    unsigned c0 = e0 - j * 3u;

    int xq = (int)(pw << 4) + (int)j - 4;
    int x0 = reflect_idx(xq);
    int x1 = reflect_idx(xq + 1);

    const float* base = x + (size_t)b * (3u * HWu) + ((unsigned)y << 10);

    float v[4];
    #pragma unroll
    for (unsigned k = 0; k < 4; ++k) {
        unsigned cc = c0 + k;
        bool adv = cc >= 3u;
        cc = adv ? cc - 3u : cc;
        int xx = adv ? x1 : x0;
        v[k] = __ldg(base + (cc << 20) + (unsigned)xx);
    }
    float4 o; o.x = v[0]; o.y = v[1]; o.z = v[2]; o.w = v[3];
    return o;
}

__global__ void __launch_bounds__(256)
patcher_kernel(const float* __restrict__ x, float* __restrict__ out,
               unsigned out_size) {
    unsigned g = blockIdx.x * 256u + threadIdx.x;

    if (g < 32u) {   // tail fill: flattened (nH,nW)=(64,64) appended
        unsigned idx = (unsigned)TOTAL_ELEMS + g;
        if (idx < out_size) out[idx] = 64.0f;
    }

    float4* o4 = reinterpret_cast<float4*>(out);

    // Two independent f4s per thread -> 8 loads in flight, stores coalesced.
    float4 r0 = gather_f4(x, g);
    float4 r1 = gather_f4(x, g + HALF_F4);
    o4[g] = r0;
    o4[g + HALF_F4] = r1;
}

extern "C" void kernel_launch(void* const* d_in, const int* in_sizes, int n_in,
                              void* d_out, int out_size) {
    const float* x = (const float*)d_in[0];
    float* out = (float*)d_out;
    patcher_kernel<<<NBLOCKS, 256>>>(x, out, (unsigned)out_size);
}

// round 13
// speedup vs baseline: 1.1092x; 1.1092x over previous
#include <cuda_runtime.h>
#include <cstdint>

// Patcher: x (8,3,1024,1024) fp32, patch=24, stride=16, reflect pad m=4.
// out[((b*64+ph)*64+pw)*1728 + (i*24+j)*3 + c] = x[b,c,ry,rx]
//   ry=reflect(ph*16+i-4), rx=reflect(pw*16+j-4); reflect: q<0->-q, q>1023->2046-q.
//
// Block (512 thr) = (b, ph, pg): 8 consecutive patches (pw = 8*pg..8*pg+7).
// smem tile s[r][x][c], c-fastest (= output order), 136 cols.
//   Phase 1: BOTH groups' 3x LDG.128 issued back-to-back (6 loads in flight,
//            MLP-first), then transpose -> STS.128.
//   Phase 2: LDS.128 + STG.128, lane-consecutive (floor wavefronts).
// 3 CTAs/SM (<=42 regs) x 16 warps = 48 warps; MLP/SM ~288 outstanding loads.

static constexpr unsigned HWu = 1024u * 1024u;
static constexpr long long TOTAL_ELEMS = 56623104LL;
static constexpr unsigned ROW_F4 = 102u;              // 136*3/4 float4 per smem row
static constexpr unsigned SMEM_F4 = 24u * ROW_F4;     // 2448 float4 = 39168 B
static constexpr unsigned N_GROUPS = 24u * 34u;       // (r, xg) groups = 816
static constexpr unsigned N_OUT4 = 8u * 432u;         // 3456 float4 per block

__device__ __forceinline__ int reflect_idx(int q) {
    q = (q < 0) ? -q : q;
    q = (q > 1023) ? (2046 - q) : q;
    return q;
}

__device__ __forceinline__ void load_group(const float* __restrict__ xb,
                                           int ybase, int gx0, unsigned idx,
                                           float4& a0, float4& a1, float4& a2) {
    unsigned r  = idx / 34u;
    unsigned xg = idx - r * 34u;
    int y  = reflect_idx(ybase + (int)r);
    int gx = gx0 + (int)(xg << 2);
    const float* p = xb + (unsigned)y * 1024u;
    if (gx >= 0 && gx <= 1020) {
        a0 = *reinterpret_cast<const float4*>(p + gx);
        a1 = *reinterpret_cast<const float4*>(p + HWu + gx);
        a2 = *reinterpret_cast<const float4*>(p + 2u * HWu + gx);
    } else {
        int x0 = reflect_idx(gx), x1 = reflect_idx(gx + 1);
        int x2 = reflect_idx(gx + 2), x3 = reflect_idx(gx + 3);
        a0.x = p[x0]; a0.y = p[x1]; a0.z = p[x2]; a0.w = p[x3];
        const float* q1 = p + HWu;
        a1.x = q1[x0]; a1.y = q1[x1]; a1.z = q1[x2]; a1.w = q1[x3];
        const float* q2 = p + 2u * HWu;
        a2.x = q2[x0]; a2.y = q2[x1]; a2.z = q2[x2]; a2.w = q2[x3];
    }
}

__device__ __forceinline__ void store_group(float4* __restrict__ s4,
                                            unsigned idx,
                                            float4 a0, float4 a1, float4 a2) {
    unsigned r  = idx / 34u;
    unsigned xg = idx - r * 34u;
    unsigned sbase = r * ROW_F4 + xg * 3u;
    float4 t0, t1, t2;
    t0.x = a0.x; t0.y = a1.x; t0.z = a2.x; t0.w = a0.y;
    t1.x = a1.y; t1.y = a2.y; t1.z = a0.z; t1.w = a1.z;
    t2.x = a2.z; t2.y = a0.w; t2.z = a1.w; t2.w = a2.w;
    s4[sbase + 0] = t0;
    s4[sbase + 1] = t1;
    s4[sbase + 2] = t2;
}

__global__ void __launch_bounds__(512, 3)
patcher_kernel(const float* __restrict__ x, float* __restrict__ out,
               unsigned out_size) {
    __shared__ float4 s4[SMEM_F4];

    unsigned bid = blockIdx.x;
    unsigned tid = threadIdx.x;
    unsigned pg = bid & 7u;          // 8 groups of 8 patches
    unsigned ph = (bid >> 3) & 63u;
    unsigned b  = bid >> 9;

    if (bid == 0 && tid < 32u) {     // tail fill: flattened (nH,nW)=(64,64)
        unsigned idx = (unsigned)TOTAL_ELEMS + tid;
        if (idx < out_size) out[idx] = 64.0f;
    }

    // ---- Phase 1: MLP-first staged loads, then transpose + STS ----
    const float* xb = x + (size_t)b * (3u * HWu);
    int ybase = (int)(ph << 4) - 4;
    int gx0   = (int)(pg << 7) - 4;   // tile x origin (pg*128 - 4)

    unsigned idx0 = tid;              // always < 816
    unsigned idx1 = tid + 512u;       // valid iff tid < 304
    bool has1 = idx1 < N_GROUPS;

    float4 a00, a01, a02, a10, a11, a12;
    load_group(xb, ybase, gx0, idx0, a00, a01, a02);
    if (has1) load_group(xb, ybase, gx0, idx1, a10, a11, a12);

    store_group(s4, idx0, a00, a01, a02);
    if (has1) store_group(s4, idx1, a10, a11, a12);
    __syncthreads();

    // ---- Phase 2: coalesced copy out ----
    unsigned patch0 = (b << 12) + (ph << 6) + (pg << 3);
    float4* o4 = reinterpret_cast<float4*>(out) + (size_t)patch0 * 432u;

    #pragma unroll
    for (unsigned it = 0; it < 7; ++it) {
        unsigned idx = tid + it * 512u;
        if (idx < N_OUT4) {
            unsigned pl  = idx / 432u;          // local patch 0..7
            unsigned rem = idx - pl * 432u;
            unsigned i   = rem / 18u;           // patch row
            unsigned off = rem - i * 18u;       // float4 in row
            o4[idx] = s4[i * ROW_F4 + pl * 12u + off];
        }
    }
}

extern "C" void kernel_launch(void* const* d_in, const int* in_sizes, int n_in,
                              void* d_out, int out_size) {
    const float* x = (const float*)d_in[0];
    float* out = (float*)d_out;
    patcher_kernel<<<4096, 512>>>(x, out, (unsigned)out_size);
}